// round 6
// baseline (speedup 1.0000x reference)
#include <cuda_runtime.h>
#include <cuda_bf16.h>
#include <stdint.h>

// ---------------- problem constants ----------------
#define CC   256
#define HWD  4096
#define NQ   65536
#define KK   1024
#define ZQ_ELEMS ((size_t)16777216)
#define MARGIN_T 1.0e-4f

// ---------------- device scratch ----------------
__device__ __align__(16) __nv_bfloat16 g_zh[NQ * CC];   // 32MB
__device__ __align__(16) __nv_bfloat16 g_zl[NQ * CC];   // 32MB
__device__ __align__(16) __nv_bfloat16 g_ch[KK * CC];
__device__ __align__(16) __nv_bfloat16 g_cl[KK * CC];
__device__ float  g_cbT[CC * KK];
__device__ float  g_cnorm[KK];
__device__ float  g_znorm[NQ];
__device__ int    g_idx[NQ];
__device__ int    g_k2[NQ];
__device__ unsigned char g_flag[NQ];
__device__ double g_losssum;

// ---------------- helpers ----------------
__device__ __forceinline__ uint32_t smem_u32(const void* p) {
    uint32_t a;
    asm("{ .reg .u64 t; cvta.to.shared.u64 t, %1; cvt.u32.u64 %0, t; }"
        : "=r"(a) : "l"(p));
    return a;
}
__device__ __forceinline__ void ldsm4(uint32_t* r, uint32_t addr) {
    asm volatile("ldmatrix.sync.aligned.m8n8.x4.shared.b16 {%0,%1,%2,%3}, [%4];"
        : "=r"(r[0]), "=r"(r[1]), "=r"(r[2]), "=r"(r[3]) : "r"(addr));
}
__device__ __forceinline__ void mma16816(float* d, const uint32_t* a, const uint32_t* b) {
    asm volatile("mma.sync.aligned.m16n8k16.row.col.f32.bf16.bf16.f32 "
        "{%0,%1,%2,%3}, {%4,%5,%6,%7}, {%8,%9}, {%0,%1,%2,%3};"
        : "+f"(d[0]), "+f"(d[1]), "+f"(d[2]), "+f"(d[3])
        : "r"(a[0]), "r"(a[1]), "r"(a[2]), "r"(a[3]), "r"(b[0]), "r"(b[1]));
}
#define CP_ASYNC16(dst, src) \
    asm volatile("cp.async.cg.shared.global [%0], [%1], 16;" :: "r"(dst), "l"(src))
#define CP_COMMIT() asm volatile("cp.async.commit_group;" ::: "memory")
#define CP_WAIT(n)  asm volatile("cp.async.wait_group %0;" :: "n"(n) : "memory")

// ---------------- prep kernels ----------------
__global__ void prep_transpose(const float* __restrict__ cb) {
    int i = blockIdx.x * 256 + threadIdx.x;
    int c = i >> 10, k = i & 1023;
    g_cbT[i] = cb[k * CC + c];
}
__global__ void prep_cnorm(const float* __restrict__ cb) {
    int k = blockIdx.x * 256 + threadIdx.x;
    if (k < KK) {
        const float* r = cb + (size_t)k * CC;
        float s = 0.f;
        #pragma unroll 8
        for (int c = 0; c < CC; c++) s = fmaf(r[c], r[c], s);
        g_cnorm[k] = s;
    }
}
__global__ void prep_split_cb(const float* __restrict__ cb) {
    int i = blockIdx.x * 256 + threadIdx.x;
    float v = cb[i];
    __nv_bfloat16 h = __float2bfloat16(v);
    g_ch[i] = h;
    g_cl[i] = __float2bfloat16(v - __bfloat162float(h));
}
__global__ void zero_loss() { g_losssum = 0.0; }

__global__ void prep_split_z(const float* __restrict__ z) {
    extern __shared__ float As[];                // [256 c][64 q]
    const int t = threadIdx.x;
    const int n0 = blockIdx.x * 64;
    const int b = n0 >> 12, hw0 = n0 & 4095;
    const float* zb = z + (size_t)b * CC * HWD + hw0;
    for (int i = t; i < 256 * 16; i += 256) {
        int c = i >> 4, lane = (i & 15) * 4;
        *(float4*)(As + c * 64 + lane) = *(const float4*)(zb + (size_t)c * HWD + lane);
    }
    __syncthreads();
    if (t < 64) {
        float s = 0.f;
        #pragma unroll 8
        for (int c = 0; c < 256; c++) { float v = As[c * 64 + t]; s = fmaf(v, v, s); }
        g_znorm[n0 + t] = s;
    }
    #pragma unroll
    for (int p = 0; p < 8; p++) {
        int idx = t + p * 256;
        int row = idx >> 5, j = idx & 31, c0 = j * 8;
        union { uint4 u; __nv_bfloat16 h[8]; } H, L;
        #pragma unroll
        for (int i = 0; i < 8; i++) {
            float v = As[(c0 + i) * 64 + row];
            __nv_bfloat16 hh = __float2bfloat16(v);
            H.h[i] = hh;
            L.h[i] = __float2bfloat16(v - __bfloat162float(hh));
        }
        size_t off = (size_t)(n0 + row) * CC + c0;
        *(uint4*)(g_zh + off) = H.u;
        *(uint4*)(g_zl + off) = L.u;
    }
}

// ---------------- main HMMA kernel ----------------
// smem layout (bytes):
#define SM_B    131072          // A: zh [0,64K), zl [64K,128K)
#define SM_CNS  163840          // B: 2 x 16KB double buffer at [128K,160K)
#define SM_RED  167936          // cns: 1024 floats
#define SM_TOT  178176          // red: 5 x 512 x 4B

__device__ __forceinline__ void issue_chunk(int g, int tid, uint32_t sb) {
    int tile = g >> 3, sub = g & 7;
    const __nv_bfloat16* base =
        ((sub & 4) ? g_cl : g_ch) + (size_t)tile * 128 * CC + (sub & 3) * 64;
    uint32_t bufb = sb + SM_B + (uint32_t)((g & 1) * 16384);
    #pragma unroll
    for (int p = 0; p < 4; p++) {
        int idx = tid + p * 256;
        int row = idx >> 3, ku = idx & 7;
        uint32_t dst = bufb + (uint32_t)row * 128u + (uint32_t)((ku ^ (row & 7)) << 4);
        CP_ASYNC16(dst, (const void*)(base + (size_t)row * CC + ku * 8));
    }
}

__device__ __forceinline__ void merge3(float& a1, float& a2, float& a3, int& ak1, int& ak2,
                                       float b1, float b2, float b3, int bk1, int bk2) {
    if (b1 < a1 || (b1 == a1 && bk1 < ak1)) {
        a3 = a2; a2 = a1; ak2 = ak1; a1 = b1; ak1 = bk1;
    } else if (b1 < a2 || (b1 == a2 && bk1 < ak2)) {
        a3 = a2; a2 = b1; ak2 = bk1;
    } else if (b1 < a3) a3 = b1;
    if (b2 < a2 || (b2 == a2 && bk2 < ak2)) { a3 = a2; a2 = b2; ak2 = bk2; }
    else if (b2 < a3) a3 = b2;
    if (b3 < a3) a3 = b3;
}

__global__ __launch_bounds__(256, 1)
void vq_tc(float* __restrict__ outIdxF, int writeIdxF) {
    extern __shared__ char smem[];
    const uint32_t sb = smem_u32(smem);
    const int tid = threadIdx.x;
    const int lane = tid & 31, warp = tid >> 5;
    const int wm = warp >> 2, wn = warp & 3;
    const int g4 = lane >> 3;
    const int n0 = blockIdx.x * 128;

    // A tiles: zh at 0, zl at 65536; 128 rows x 256 cols bf16, row stride 512B,
    // ku-xor swizzle. 128 rows x 32 ku-units = 4096 uint4 per tensor -> p < 16.
    #pragma unroll
    for (int p = 0; p < 16; p++) {
        int idx = tid + p * 256;                // 0..4095
        int row = idx >> 5, ku = idx & 31;
        uint32_t off = (uint32_t)row * 512u + (uint32_t)((ku ^ (row & 7)) << 4);
        *(uint4*)(smem + off)          = *(const uint4*)(g_zh + (size_t)(n0 + row) * CC + ku * 8);
        *(uint4*)(smem + 65536 + off)  = *(const uint4*)(g_zl + (size_t)(n0 + row) * CC + ku * 8);
    }
    #pragma unroll
    for (int p = 0; p < 4; p++)
        ((float*)(smem + SM_CNS))[tid + p * 256] = g_cnorm[tid + p * 256];

    float zn[8];
    #pragma unroll
    for (int s = 0; s < 8; s++) {
        int row = wm * 64 + (s >> 1) * 16 + (s & 1) * 8 + (lane >> 2);
        zn[s] = g_znorm[n0 + row];
    }

    float s1[8], s2[8], s3[8]; int k1[8], k2v[8];
    #pragma unroll
    for (int s = 0; s < 8; s++) { s1[s] = s2[s] = s3[s] = 3.4e38f; k1[s] = k2v[s] = 0; }

    float acc[4][4][4];
    #pragma unroll
    for (int a = 0; a < 4; a++)
        #pragma unroll
        for (int b = 0; b < 4; b++)
            #pragma unroll
            for (int c = 0; c < 4; c++) acc[a][b][c] = 0.f;

    issue_chunk(0, tid, sb); CP_COMMIT();
    issue_chunk(1, tid, sb); CP_COMMIT();

    #define UPD3(s, dd, kk_) do { float _d = (dd); int _k = (kk_); \
        if (_d < s1[s]) { s3[s] = s2[s]; s2[s] = s1[s]; k2v[s] = k1[s]; s1[s] = _d; k1[s] = _k; } \
        else if (_d < s2[s]) { s3[s] = s2[s]; s2[s] = _d; k2v[s] = _k; } \
        else if (_d < s3[s]) { s3[s] = _d; } } while (0)

    for (int i = 0; i < 64; i++) {
        if (i < 63) CP_WAIT(1); else CP_WAIT(0);
        __syncthreads();
        const int pass = (i >> 2) & 1;           // 0: ch chunk (zh+zl), 1: cl chunk (zh)
        const int cofs = (i & 3) * 8;            // A ku-offset for this 64-wide K chunk
        const uint32_t bufb = sb + SM_B + (uint32_t)((i & 1) * 16384);
        #pragma unroll
        for (int k16 = 0; k16 < 4; k16++) {
            uint32_t bfr[2][4];
            #pragma unroll
            for (int np = 0; np < 2; np++) {
                int nrow = wn * 32 + np * 16 + (g4 >> 1) * 8 + (lane & 7);
                int kuB = k16 * 2 + (g4 & 1);
                ldsm4(bfr[np], bufb + (uint32_t)nrow * 128u +
                               (uint32_t)((kuB ^ (nrow & 7)) << 4));
            }
            #pragma unroll
            for (int mt = 0; mt < 4; mt++) {
                int arow = wm * 64 + mt * 16 + (g4 & 1) * 8 + (lane & 7);
                int kuA = cofs + k16 * 2 + (g4 >> 1);
                uint32_t aaddr = sb + (uint32_t)arow * 512u +
                                 (uint32_t)((kuA ^ (arow & 7)) << 4);
                uint32_t afr[4];
                ldsm4(afr, aaddr);
                #pragma unroll
                for (int nt = 0; nt < 4; nt++)
                    mma16816(acc[mt][nt], afr, &bfr[nt >> 1][(nt & 1) * 2]);
                if (pass == 0) {
                    ldsm4(afr, aaddr + 65536u);
                    #pragma unroll
                    for (int nt = 0; nt < 4; nt++)
                        mma16816(acc[mt][nt], afr, &bfr[nt >> 1][(nt & 1) * 2]);
                }
            }
        }
        __syncthreads();
        if (i + 2 < 64) { issue_chunk(i + 2, tid, sb); CP_COMMIT(); }
        if ((i & 7) == 7) {
            int tile = i >> 3;
            const float* cns = (const float*)(smem + SM_CNS) + tile * 128;
            #pragma unroll
            for (int mt = 0; mt < 4; mt++) {
                #pragma unroll
                for (int nt = 0; nt < 4; nt++) {
                    int c0 = wn * 32 + nt * 8 + (lane & 3) * 2;
                    int kg = tile * 128 + c0;
                    float cn0 = cns[c0], cn1 = cns[c0 + 1];
                    UPD3(mt * 2,     zn[mt * 2]     + cn0 - 2.f * acc[mt][nt][0], kg);
                    UPD3(mt * 2,     zn[mt * 2]     + cn1 - 2.f * acc[mt][nt][1], kg + 1);
                    UPD3(mt * 2 + 1, zn[mt * 2 + 1] + cn0 - 2.f * acc[mt][nt][2], kg);
                    UPD3(mt * 2 + 1, zn[mt * 2 + 1] + cn1 - 2.f * acc[mt][nt][3], kg + 1);
                    acc[mt][nt][0] = acc[mt][nt][1] = acc[mt][nt][2] = acc[mt][nt][3] = 0.f;
                }
            }
        }
    }

    // quad merge (cols within quad)
    #pragma unroll
    for (int s = 0; s < 8; s++) {
        #pragma unroll
        for (int off = 1; off <= 2; off <<= 1) {
            float ob1 = __shfl_xor_sync(0xffffffffu, s1[s], off);
            float ob2 = __shfl_xor_sync(0xffffffffu, s2[s], off);
            float ob3 = __shfl_xor_sync(0xffffffffu, s3[s], off);
            int   ok1 = __shfl_xor_sync(0xffffffffu, k1[s], off);
            int   ok2 = __shfl_xor_sync(0xffffffffu, k2v[s], off);
            merge3(s1[s], s2[s], s3[s], k1[s], k2v[s], ob1, ob2, ob3, ok1, ok2);
        }
    }
    float* rB1 = (float*)(smem + SM_RED);
    float* rB2 = rB1 + 512;
    float* rB3 = rB2 + 512;
    int*   rK1 = (int*)(rB3 + 512);
    int*   rK2 = rK1 + 512;
    if ((lane & 3) == 0) {
        #pragma unroll
        for (int s = 0; s < 8; s++) {
            int row = wm * 64 + (s >> 1) * 16 + (s & 1) * 8 + (lane >> 2);
            rB1[row * 4 + wn] = s1[s]; rB2[row * 4 + wn] = s2[s]; rB3[row * 4 + wn] = s3[s];
            rK1[row * 4 + wn] = k1[s]; rK2[row * 4 + wn] = k2v[s];
        }
    }
    __syncthreads();
    if (tid < 128) {
        float B1 = rB1[tid * 4], B2 = rB2[tid * 4], B3 = rB3[tid * 4];
        int K1 = rK1[tid * 4], K2 = rK2[tid * 4];
        #pragma unroll
        for (int wq = 1; wq < 4; wq++)
            merge3(B1, B2, B3, K1, K2,
                   rB1[tid * 4 + wq], rB2[tid * 4 + wq], rB3[tid * 4 + wq],
                   rK1[tid * 4 + wq], rK2[tid * 4 + wq]);
        int q = n0 + tid;
        g_idx[q] = K1;
        g_k2[q] = K2;
        g_flag[q] = (B3 - B1 < MARGIN_T) ? 2 : ((B2 - B1 < MARGIN_T) ? 1 : 0);
        if (writeIdxF) outIdxF[q] = (float)K1;
    }
}

// ---------------- rescue 1: exact fp32 pairwise decision ----------------
__global__ void rescue_pair(const float* __restrict__ z, const float* __restrict__ cb,
                            float* __restrict__ outIdxF, int writeIdxF) {
    int q = blockIdx.x * 256 + threadIdx.x;
    if (g_flag[q] != 1) return;
    int b = q >> 12, hw = q & 4095;
    const float* zb = z + (size_t)b * CC * HWD + hw;
    int ka = g_idx[q], kb = g_k2[q];
    const float* ca = cb + (size_t)ka * CC;
    const float* cbr = cb + (size_t)kb * CC;
    float zn = 0.f, da = 0.f, db = 0.f;
    #pragma unroll 4
    for (int c = 0; c < CC; c++) {
        float v = zb[(size_t)c * HWD];
        zn = fmaf(v, v, zn); da = fmaf(v, ca[c], da); db = fmaf(v, cbr[c], db);
    }
    float d1 = (zn + g_cnorm[ka]) - 2.f * da;
    float d2 = (zn + g_cnorm[kb]) - 2.f * db;
    int kw = (d2 < d1 || (d2 == d1 && kb < ka)) ? kb : ka;
    g_idx[q] = kw;
    if (writeIdxF) outIdxF[q] = (float)kw;
}

// ---------------- rescue 2: exact fp32 full scan ----------------
__global__ void rescue_full(const float* __restrict__ z, const float* __restrict__ cb,
                            float* __restrict__ outIdxF, int writeIdxF) {
    __shared__ float zrow[8][256];
    const int lane = threadIdx.x & 31;
    const int w = threadIdx.x >> 5;
    const int warpGlobal = blockIdx.x * 8 + w;
    for (int qi = 0; qi < 32; qi++) {
        int q = warpGlobal * 32 + qi;
        if (g_flag[q] != 2) continue;
        int b = q >> 12, hw = q & 4095;
        const float* zb = z + (size_t)b * CC * HWD + hw;
        for (int c = lane; c < 256; c += 32) zrow[w][c] = zb[(size_t)c * HWD];
        __syncwarp();
        float zn = 0.f;
        #pragma unroll 8
        for (int c = 0; c < 256; c++) { float v = zrow[w][c]; zn = fmaf(v, v, zn); }
        float best = 3.4e38f; int bk = 0;
        for (int k = lane; k < KK; k += 32) {
            const float* cr = cb + (size_t)k * CC;
            float dot = 0.f;
            #pragma unroll 8
            for (int c = 0; c < 256; c++) dot = fmaf(zrow[w][c], cr[c], dot);
            float d = (zn + g_cnorm[k]) - 2.f * dot;
            if (d < best) { best = d; bk = k; }
        }
        #pragma unroll
        for (int off = 16; off > 0; off >>= 1) {
            float od = __shfl_down_sync(0xffffffffu, best, off);
            int   ok = __shfl_down_sync(0xffffffffu, bk, off);
            if (od < best || (od == best && ok < bk)) { best = od; bk = ok; }
        }
        if (lane == 0) {
            g_idx[q] = bk;
            if (writeIdxF) outIdxF[q] = (float)bk;
        }
        __syncwarp();
    }
}

// ---------------- writer + loss ----------------
__global__ void vq_writer(const float* __restrict__ z, float* __restrict__ out) {
    __shared__ float warpsum[8];
    size_t base = (size_t)blockIdx.x * 2048;
    float s = 0.f;
    #pragma unroll
    for (int e = 0; e < 8; e++) {
        size_t idx = base + (size_t)e * 256 + threadIdx.x;
        int c = (int)((idx >> 12) & 255);
        int n = (int)(((idx >> 20) << 12) | (idx & 4095));
        int k = g_idx[n];
        float v = g_cbT[c * KK + k];
        float zv = z[idx];
        out[idx] = v;
        float d = v - zv;
        s += d * d;
    }
    #pragma unroll
    for (int o = 16; o > 0; o >>= 1) s += __shfl_down_sync(0xffffffffu, s, o);
    if ((threadIdx.x & 31) == 0) warpsum[threadIdx.x >> 5] = s;
    __syncthreads();
    if (threadIdx.x == 0) {
        float bs = 0.f;
        #pragma unroll
        for (int w = 0; w < 8; w++) bs += warpsum[w];
        atomicAdd(&g_losssum, (double)bs);
    }
}

__global__ void vq_finalize(float* __restrict__ outLoss) {
    double m = g_losssum / (double)ZQ_ELEMS;
    float mf = (float)m;
    *outLoss = mf - 0.25f * mf;
}

// ---------------- launch ----------------
extern "C" void kernel_launch(void* const* d_in, const int* in_sizes, int n_in,
                              void* d_out, int out_size) {
    const float* z  = (const float*)d_in[0];
    const float* cb = (const float*)d_in[1];
    if (n_in >= 2 && in_sizes[0] == KK * CC && in_sizes[1] == (int)ZQ_ELEMS) {
        z = (const float*)d_in[1]; cb = (const float*)d_in[0];
    }
    float* out = (float*)d_out;

    cudaFuncSetAttribute(vq_tc, cudaFuncAttributeMaxDynamicSharedMemorySize, SM_TOT);
    cudaFuncSetAttribute(prep_split_z, cudaFuncAttributeMaxDynamicSharedMemorySize, 65536);

    prep_transpose<<<(CC * KK) / 256, 256>>>(cb);
    prep_cnorm<<<(KK + 255) / 256, 256>>>(cb);
    prep_split_cb<<<(KK * CC) / 256, 256>>>(cb);
    zero_loss<<<1, 1>>>();
    prep_split_z<<<NQ / 64, 256, 65536>>>(z);

    int writeIdxF = (out_size >= (int)(ZQ_ELEMS + NQ)) ? 1 : 0;
    float* outIdxF = out + ZQ_ELEMS;

    vq_tc<<<NQ / 128, 256, SM_TOT>>>(outIdxF, writeIdxF);
    rescue_pair<<<NQ / 256, 256>>>(z, cb, outIdxF, writeIdxF);
    rescue_full<<<256, 256>>>(z, cb, outIdxF, writeIdxF);
    vq_writer<<<(int)(ZQ_ELEMS / 2048), 256>>>(z, out);

    if (out_size >= (int)(ZQ_ELEMS + NQ + 1)) {
        vq_finalize<<<1, 1>>>(out + ZQ_ELEMS + NQ);
    }
}